// round 1
// baseline (speedup 1.0000x reference)
#include <cuda_runtime.h>
#include <math.h>

#define H_   32
#define W_   32
#define P_   1024          // H*W
#define C_   768
#define C4_  192           // C/4
#define K9_  9
#define KK_  6912          // 9*C
#define KK4_ 1728          // KK/4
#define M_   4096          // N*P
#define NSEG 1406          // sum of 1x1 out-channels

// ---------------- scratch (static device allocations; no cudaMalloc) ----------
__device__ float g_big[(size_t)M_ * KK_];      // im2col / sampled-masked A (reused)
__device__ float g_om[(size_t)M_ * C_];        // conv3x3 output (per block, reused)
__device__ float g_blk[5][(size_t)M_ * C_];    // deform block outputs
__device__ float g_off[4 * 18 * P_];           // offsets [n][o][p]
__device__ float g_mask[4 * K9_ * P_];         // softmax, stored [n][p*9+k]
__device__ float g_BtConv[(size_t)KK_ * C_];   // conv_w transposed: [(k*768+c)][o]
__device__ float g_Bt1[C_ * NSEG];             // 1x1 weights transposed: [c][seg]
__device__ float g_scale[C_];
__device__ float g_shift[C_];

// ---------------- weight prep ------------------------------------------------
__global__ void tconv_k(const float* __restrict__ w) {
    size_t i = (size_t)blockIdx.x * 256 + threadIdx.x;
    if (i >= (size_t)KK_ * C_) return;
    int o  = (int)(i % C_);
    int kk = (int)(i / C_);
    int c  = kk % C_;
    int k  = kk / C_;
    g_BtConv[i] = w[((size_t)o * C_ + c) * 9 + k];
}

__global__ void t1x1_k(const float* __restrict__ w, int ch, int col0) {
    int i = blockIdx.x * 256 + threadIdx.x;
    if (i >= C_ * ch) return;
    int c = i / ch, j = i % ch;
    g_Bt1[c * NSEG + col0 + j] = w[j * C_ + c];
}

__global__ void bnprep_k(const float* g, const float* bt, const float* mu,
                         const float* var, const float* cb) {
    int c = blockIdx.x * 256 + threadIdx.x;
    if (c >= C_) return;
    float inv = g[c] / sqrtf(var[c] + 1e-5f);
    g_scale[c] = inv;
    g_shift[c] = cb[c] * inv + bt[c] - mu[c] * inv;
}

// ---------------- im2col for conv3x3 -----------------------------------------
__global__ void im2col_k(const float* __restrict__ x) {
    int p = blockIdx.x, k = blockIdx.y, n = blockIdx.z;
    int t = threadIdx.x;                      // 0..191 (float4 over channels)
    int h = p >> 5, w = p & 31;
    int hh = h + k / 3 - 1, ww = w + k % 3 - 1;
    float4 v = make_float4(0.f, 0.f, 0.f, 0.f);
    if (hh >= 0 && hh < H_ && ww >= 0 && ww < W_)
        v = ((const float4*)x)[((size_t)n * P_ + hh * W_ + ww) * C4_ + t];
    ((float4*)g_big)[((size_t)n * P_ + p) * KK4_ + k * C4_ + t] = v;
}

// ---------------- offset / mask heads (warp per pixel) -----------------------
__global__ void offsets_k(const float* __restrict__ ow, const float* __restrict__ mw) {
    int lane = threadIdx.x & 31;
    int row  = blockIdx.x * 8 + (threadIdx.x >> 5);   // 0..4095
    int n = row >> 10, p = row & 1023;
    const float* omr = g_om + (size_t)row * C_;
    float v[24];
#pragma unroll
    for (int i = 0; i < 24; i++) v[i] = omr[lane + 32 * i];
    float res[27];
#pragma unroll
    for (int o = 0; o < 27; o++) {
        const float* wr = (o < 18) ? (ow + o * C_) : (mw + (o - 18) * C_);
        float s = 0.f;
#pragma unroll
        for (int i = 0; i < 24; i++) s += v[i] * wr[lane + 32 * i];
#pragma unroll
        for (int d = 16; d; d >>= 1) s += __shfl_xor_sync(0xffffffffu, s, d);
        res[o] = s;
    }
    if (lane == 0) {
#pragma unroll
        for (int o = 0; o < 18; o++) g_off[n * (18 * P_) + o * P_ + p] = res[o];
        float mx = res[18];
#pragma unroll
        for (int k = 1; k < 9; k++) mx = fmaxf(mx, res[18 + k]);
        float e[9], sum = 0.f;
#pragma unroll
        for (int k = 0; k < 9; k++) { e[k] = expf(res[18 + k] - mx); sum += e[k]; }
        float r = 1.f / sum;
        // store softmax in NATURAL (h,w,k) layout: raw-reshape quirk handled at read
#pragma unroll
        for (int k = 0; k < 9; k++) g_mask[n * (K9_ * P_) + p * K9_ + k] = e[k] * r;
    }
}

// ---------------- deformable bilinear sampling * mask ------------------------
__global__ void sample_k(const float* __restrict__ x) {
    int p = blockIdx.x, k = blockIdx.y, n = blockIdx.z;
    int t = threadIdx.x;                      // 0..191
    float dy = g_off[n * (18 * P_) + (2 * k) * P_ + p];
    float dx = g_off[n * (18 * P_) + (2 * k + 1) * P_ + p];
    // raw-reshape quirk: mask[n,k,h,w] = natural-layout buffer at [n][k*1024+p]
    float m  = g_mask[n * (K9_ * P_) + k * P_ + p];
    int h = p >> 5, w = p & 31;
    float py = (float)(h - 1 + k / 3) + dy;
    float px = (float)(w - 1 + k % 3) + dx;
    float y0f = floorf(py), x0f = floorf(px);
    float wy = py - y0f, wx = px - x0f;
    int y0 = (int)y0f, x0 = (int)x0f;
    const float4* xb = (const float4*)x + (size_t)n * P_ * C4_;
    float w00 = (1.f - wy) * (1.f - wx), w01 = (1.f - wy) * wx;
    float w10 = wy * (1.f - wx),         w11 = wy * wx;
    bool vy0 = (y0 >= 0) && (y0 < H_),  vy1 = (y0 >= -1) && (y0 < H_ - 1);
    bool vx0 = (x0 >= 0) && (x0 < W_),  vx1 = (x0 >= -1) && (x0 < W_ - 1);
    float ax = 0.f, ay = 0.f, az = 0.f, aw = 0.f;
    if (vy0 && vx0) { float4 s = xb[(y0 * W_ + x0) * C4_ + t];
        ax += w00 * s.x; ay += w00 * s.y; az += w00 * s.z; aw += w00 * s.w; }
    if (vy0 && vx1) { float4 s = xb[(y0 * W_ + x0 + 1) * C4_ + t];
        ax += w01 * s.x; ay += w01 * s.y; az += w01 * s.z; aw += w01 * s.w; }
    if (vy1 && vx0) { float4 s = xb[((y0 + 1) * W_ + x0) * C4_ + t];
        ax += w10 * s.x; ay += w10 * s.y; az += w10 * s.z; aw += w10 * s.w; }
    if (vy1 && vx1) { float4 s = xb[((y0 + 1) * W_ + x0 + 1) * C4_ + t];
        ax += w11 * s.x; ay += w11 * s.y; az += w11 * s.z; aw += w11 * s.w; }
    float4 o;
    o.x = ax * m; o.y = ay * m; o.z = az * m; o.w = aw * m;
    ((float4*)g_big)[((size_t)n * P_ + p) * KK4_ + k * C4_ + t] = o;
}

// ---------------- generic fp32 SGEMM: C = A[M x K] * B[K x N(ldb)] -----------
// epilogue: optional bias[col], optional BN(scale/shift)+..., optional relu,
// optional accumulate into C; C column offset coff, leading dim ldc.
__global__ void __launch_bounds__(256) sgemm_k(
    const float* __restrict__ A, const float* __restrict__ B, float* __restrict__ C,
    int N, int K, int ldb, int bcol0, int ldc, int coff,
    const float* __restrict__ bias, int use_bn, int relu, int acc)
{
    __shared__ float As[8][128];
    __shared__ float Bs[8][128];
    int tid = threadIdx.x;
    int bm = blockIdx.y * 128, bn = blockIdx.x * 128;
    int arow = tid >> 1, acol = (tid & 1) * 4;
    int brow = tid >> 5, bcol = (tid & 31) * 4;
    int ty = tid >> 4, tx = tid & 15;
    float acc8[8][8];
#pragma unroll
    for (int i = 0; i < 8; i++)
#pragma unroll
        for (int j = 0; j < 8; j++) acc8[i][j] = 0.f;

    for (int k0 = 0; k0 < K; k0 += 8) {
        float4 a = *(const float4*)(A + (size_t)(bm + arow) * K + k0 + acol);
        As[acol + 0][arow] = a.x; As[acol + 1][arow] = a.y;
        As[acol + 2][arow] = a.z; As[acol + 3][arow] = a.w;
        const float* bp = B + (size_t)(k0 + brow) * ldb + bcol0 + bn + bcol;
        Bs[brow][bcol + 0] = (bn + bcol + 0 < N) ? bp[0] : 0.f;
        Bs[brow][bcol + 1] = (bn + bcol + 1 < N) ? bp[1] : 0.f;
        Bs[brow][bcol + 2] = (bn + bcol + 2 < N) ? bp[2] : 0.f;
        Bs[brow][bcol + 3] = (bn + bcol + 3 < N) ? bp[3] : 0.f;
        __syncthreads();
#pragma unroll
        for (int kk = 0; kk < 8; kk++) {
            float ar[8], br[8];
            *(float4*)ar       = *(const float4*)&As[kk][ty * 8];
            *(float4*)(ar + 4) = *(const float4*)&As[kk][ty * 8 + 4];
            *(float4*)br       = *(const float4*)&Bs[kk][tx * 8];
            *(float4*)(br + 4) = *(const float4*)&Bs[kk][tx * 8 + 4];
#pragma unroll
            for (int i = 0; i < 8; i++)
#pragma unroll
                for (int j = 0; j < 8; j++) acc8[i][j] += ar[i] * br[j];
        }
        __syncthreads();
    }
#pragma unroll
    for (int i = 0; i < 8; i++) {
        int row = bm + ty * 8 + i;
#pragma unroll
        for (int j = 0; j < 8; j++) {
            int col = bn + tx * 8 + j;
            if (col < N) {
                float v = acc8[i][j];
                if (bias)   v += bias[col];
                if (use_bn) v = v * g_scale[col] + g_shift[col];
                if (relu)   v = fmaxf(v, 0.f);
                size_t ci = (size_t)row * ldc + coff + col;
                if (acc) C[ci] += v; else C[ci] = v;
            }
        }
    }
}

// ---------------- residual ---------------------------------------------------
__global__ void resid_k(const float* __restrict__ x5, float* __restrict__ out) {
    size_t i = (size_t)blockIdx.x * 256 + threadIdx.x;
    if (i < (size_t)M_ * C_) out[i] += x5[i];
}

// ---------------- launch -----------------------------------------------------
extern "C" void kernel_launch(void* const* d_in, const int* in_sizes, int n_in,
                              void* d_out, int out_size) {
    static float* pBig = nullptr;
    static float* pOm = nullptr;
    static float* pBlk = nullptr;
    static float* pBtC = nullptr;
    static float* pBt1 = nullptr;
    if (!pBig) {
        cudaGetSymbolAddress((void**)&pBig, g_big);
        cudaGetSymbolAddress((void**)&pOm,  g_om);
        cudaGetSymbolAddress((void**)&pBlk, g_blk);
        cudaGetSymbolAddress((void**)&pBtC, g_BtConv);
        cudaGetSymbolAddress((void**)&pBt1, g_Bt1);
    }
    const float* x[5];
    for (int i = 0; i < 5; i++) x[i] = (const float*)d_in[i];
    const float* conv_w = (const float*)d_in[5];
    const float* conv_b = (const float*)d_in[6];
    const float* offw   = (const float*)d_in[7];
    const float* maskw  = (const float*)d_in[8];
    const float* gamma  = (const float*)d_in[9];
    const float* beta   = (const float*)d_in[10];
    const float* mean   = (const float*)d_in[11];
    const float* var    = (const float*)d_in[12];
    const float* w1x[8];
    for (int i = 0; i < 8; i++) w1x[i] = (const float*)d_in[13 + i];
    float* out = (float*)d_out;

    // weight prep (cheap, runs inside the graph each replay — deterministic)
    tconv_k<<<(int)(((size_t)KK_ * C_ + 255) / 256), 256>>>(conv_w);
    const int chs[8]  = {30, 100, 150, 150, 220, 220, 268, 268};
    const int bcol[8] = {0, 30, 130, 280, 430, 650, 870, 1138};
    for (int i = 0; i < 8; i++)
        t1x1_k<<<(C_ * chs[i] + 255) / 256, 256>>>(w1x[i], chs[i], bcol[i]);
    bnprep_k<<<3, 256>>>(gamma, beta, mean, var, conv_b);

    dim3 gIm(P_, K9_, 4);
    for (int b = 0; b < 5; b++) {
        im2col_k<<<gIm, 192>>>(x[b]);
        sgemm_k<<<dim3(6, 32), 256>>>(pBig, pBtC, pOm,
                                      C_, KK_, C_, 0, C_, 0, conv_b, 0, 0, 0);
        offsets_k<<<512, 256>>>(offw, maskw);
        sample_k<<<gIm, 192>>>(x[b]);
        sgemm_k<<<dim3(6, 32), 256>>>(pBig, pBtC, pBlk + (size_t)b * M_ * C_,
                                      C_, KK_, C_, 0, C_, 0, nullptr, 1, 1, 0);
    }

    // 1x1 segment convs into d_out (concat layout), plus raw-input branches
    const int coffs[5] = {0, 30, 130, 280, 500};
    const int waIdx[5] = {0, 1, 2, 4, 6};
    for (int b = 0; b < 5; b++) {
        int wi = waIdx[b];
        int n = chs[wi];
        sgemm_k<<<dim3((n + 127) / 128, 32), 256>>>(
            pBlk + (size_t)b * M_ * C_, pBt1, out,
            n, C_, NSEG, bcol[wi], C_, coffs[b], nullptr, 0, 0, 0);
        if (b >= 2) {
            int wj = wi + 1;
            sgemm_k<<<dim3((n + 127) / 128, 32), 256>>>(
                x[b], pBt1, out,
                n, C_, NSEG, bcol[wj], C_, coffs[b], nullptr, 0, 0, 1);
        }
    }
    resid_k<<<(int)(((size_t)M_ * C_ + 255) / 256), 256>>>(x[4], out);
}